// round 14
// baseline (speedup 1.0000x reference)
#include <cuda_runtime.h>
#include <cuda_fp16.h>
#include <math.h>
#include <stdint.h>

// ---------------------------------------------------------------------------
// Problem constants
//   x:      (4, 96, 96, 192)  -> tokens = 36864
//   qkv:    tokens x 576 (half; q pre-scaled by 2^-2.5 * log2(e))
//   att:    tokens x 192 (half)
//   out:    tokens x 192 (float)
// ---------------------------------------------------------------------------
#define TOKENS (4 * 96 * 96)

__device__ unsigned short g_qkv_h[(size_t)TOKENS * 576]; // 42.5 MB half scratch
__device__ unsigned short g_att_h[(size_t)TOKENS * 192]; // 14.2 MB half scratch
__device__ unsigned short g_wqkvt[576 * 192];            // w_qkv^T half [N][K]
__device__ unsigned short g_wprojt[192 * 192];           // w_proj^T half [N][K]

__device__ __forceinline__ uint32_t pack_half2(float lo, float hi) {
    uint32_t r;
    asm("cvt.rn.f16x2.f32 %0, %1, %2;" : "=r"(r) : "f"(hi), "f"(lo));
    return r;
}
__device__ __forceinline__ uint32_t h2add(uint32_t a, uint32_t b) {
    uint32_t r;
    asm("add.f16x2 %0, %1, %2;" : "=r"(r) : "r"(a), "r"(b));
    return r;
}
__device__ __forceinline__ uint32_t h2exp2(uint32_t x) {
    uint32_t r;
    asm("ex2.approx.f16x2 %0, %1;" : "=r"(r) : "r"(x));
    return r;
}
__device__ __forceinline__ void mma_f16(float* d, uint32_t a0, uint32_t a1,
                                        uint32_t a2, uint32_t a3,
                                        uint32_t b0, uint32_t b1) {
    asm volatile(
        "mma.sync.aligned.m16n8k16.row.col.f32.f16.f16.f32 "
        "{%0,%1,%2,%3}, {%4,%5,%6,%7}, {%8,%9}, {%0,%1,%2,%3};\n"
        : "+f"(d[0]), "+f"(d[1]), "+f"(d[2]), "+f"(d[3])
        : "r"(a0), "r"(a1), "r"(a2), "r"(a3), "r"(b0), "r"(b1));
}
__device__ __forceinline__ void ldsm_x4(uint32_t* r, const __half* p) {
    uint32_t addr = (uint32_t)__cvta_generic_to_shared(p);
    asm volatile("ldmatrix.sync.aligned.m8n8.x4.shared.b16 {%0,%1,%2,%3}, [%4];"
                 : "=r"(r[0]), "=r"(r[1]), "=r"(r[2]), "=r"(r[3]) : "r"(addr));
}
__device__ __forceinline__ void ldsm_x4_trans(uint32_t* r, const __half* p) {
    uint32_t addr = (uint32_t)__cvta_generic_to_shared(p);
    asm volatile("ldmatrix.sync.aligned.m8n8.x4.trans.shared.b16 {%0,%1,%2,%3}, [%4];"
                 : "=r"(r[0]), "=r"(r[1]), "=r"(r[2]), "=r"(r[3]) : "r"(addr));
}
__device__ __forceinline__ void cp_async16(__half* dst, const __half* src) {
    uint32_t d = (uint32_t)__cvta_generic_to_shared(dst);
    asm volatile("cp.async.cg.shared.global [%0], [%1], 16;\n" :: "r"(d), "l"(src));
}
__device__ __forceinline__ void cp_commit() {
    asm volatile("cp.async.commit_group;\n");
}
template <int N>
__device__ __forceinline__ void cp_wait() {
    asm volatile("cp.async.wait_group %0;\n" :: "n"(N));
}

// ---------------------------------------------------------------------------
// Pre-pass: both weight transposes in ONE launch.
// ---------------------------------------------------------------------------
__global__ void __launch_bounds__(256) transpose_weights_kernel(
    const float* __restrict__ wq, const float* __restrict__ wp,
    __half* __restrict__ wqt, __half* __restrict__ wpt)
{
    int i = blockIdx.x * 256 + threadIdx.x;
    if (i < 192 * 576) {
        int k = i / 576, n = i % 576;
        wqt[n * 192 + k] = __float2half(wq[i]);
    } else {
        i -= 192 * 576;
        if (i < 192 * 192) {
            int k = i / 192, n = i % 192;
            wpt[n * 192 + k] = __float2half(wp[i]);
        }
    }
}

// ---------------------------------------------------------------------------
// Persistent-A f16 GEMM, K=192, 256 threads (8 warps: 4 M x 2 N) — R12 config.
// Warp tile 32x32 (2 mi x 4 ni). Double-buffered cp.async B over NB n-tiles.
// QSCALE: q blocks scaled by 2^-2.5 * log2(e)  (scores in log2 domain).
// ---------------------------------------------------------------------------
template <bool AF32, typename OT, bool QSCALE, int NB>
__global__ void __launch_bounds__(256) gemm_persistA_kernel(
    const void* __restrict__ Ap, const __half* __restrict__ BT,
    const float* __restrict__ bias, OT* __restrict__ C)
{
    constexpr int K = 192, STR = 200, N = NB * 64;
    extern __shared__ __align__(16) __half smg[];
    __half* As  = smg;
    __half* Bs0 = smg + 128 * STR;
    __half* Bs1 = Bs0 + 64 * STR;

    const int tid    = threadIdx.x;
    const int lane   = tid & 31;
    const int warpId = tid >> 5;
    const int wm     = warpId & 3;
    const int wn     = warpId >> 2;
    const int m0     = blockIdx.x * 128;
    const int lq = lane >> 2;
    const int lr = lane & 3;

    auto issueB = [&](int nt, __half* dst) {
#pragma unroll
        for (int i = 0; i < 6; ++i) {
            int idx = tid + i * 256;
            int row = idx / 24, c = idx % 24;
            cp_async16(&dst[row * STR + c * 8],
                       &BT[(size_t)(nt * 64 + row) * K + c * 8]);
        }
        cp_commit();
    };
    issueB(0, Bs0);
    issueB(1, Bs1);

    if constexpr (AF32) {
        const float* A = (const float*)Ap;
#pragma unroll
        for (int i = 0; i < 24; ++i) {
            int idx = tid + i * 256;
            int row = idx / 48, c = idx % 48;
            float4 v = *(const float4*)&A[(size_t)(m0 + row) * K + c * 4];
            uint2 u;
            u.x = pack_half2(v.x, v.y);
            u.y = pack_half2(v.z, v.w);
            *(uint2*)&As[row * STR + c * 4] = u;
        }
    } else {
        const __half* A = (const __half*)Ap;
#pragma unroll
        for (int i = 0; i < 12; ++i) {
            int idx = tid + i * 256;
            int row = idx / 24, c = idx % 24;
            cp_async16(&As[row * STR + c * 8], &A[(size_t)(m0 + row) * K + c * 8]);
        }
        cp_commit();
    }

    const __half* aA = &As[(wm * 32 + (lane & 15)) * STR + (lane >> 4) * 8];
    const int bOff = (wn * 32 + ((lane >> 4) & 1) * 8 + (lane & 7)) * STR
                     + ((lane >> 3) & 1) * 8;

    auto compute = [&](const __half* BsBuf, int nt) {
        float acc[2][4][4];
#pragma unroll
        for (int mi = 0; mi < 2; ++mi)
#pragma unroll
            for (int ni = 0; ni < 4; ++ni)
#pragma unroll
                for (int r = 0; r < 4; ++r) acc[mi][ni][r] = 0.f;

        const __half* aB = BsBuf + bOff;
#pragma unroll
        for (int kt = 0; kt < 12; ++kt) {
            uint32_t a[2][4], b[2][4];
            ldsm_x4(a[0], aA + kt * 16);
            ldsm_x4(a[1], aA + 16 * STR + kt * 16);
            ldsm_x4(b[0], aB + kt * 16);
            ldsm_x4(b[1], aB + 16 * STR + kt * 16);
#pragma unroll
            for (int mi = 0; mi < 2; ++mi)
#pragma unroll
                for (int p = 0; p < 2; ++p) {
                    mma_f16(acc[mi][2 * p],     a[mi][0], a[mi][1], a[mi][2], a[mi][3],
                            b[p][0], b[p][1]);
                    mma_f16(acc[mi][2 * p + 1], a[mi][0], a[mi][1], a[mi][2], a[mi][3],
                            b[p][2], b[p][3]);
                }
        }

        float s = 1.f;
        if (QSCALE && (nt % 3 == 0)) s = 0.25503519364597307f; // 2^-2.5 * log2(e)
        const int n0 = nt * 64;
#pragma unroll
        for (int mi = 0; mi < 2; ++mi) {
#pragma unroll
            for (int ni = 0; ni < 4; ++ni) {
                int row = m0 + wm * 32 + mi * 16 + lq;
                int col = n0 + wn * 32 + ni * 8 + 2 * lr;
                float2 bv = *(const float2*)&bias[col];
                float f0 = (acc[mi][ni][0] + bv.x) * s;
                float f1 = (acc[mi][ni][1] + bv.y) * s;
                float f2 = (acc[mi][ni][2] + bv.x) * s;
                float f3 = (acc[mi][ni][3] + bv.y) * s;
                if constexpr (sizeof(OT) == 2) {
                    *(uint32_t*)&C[(size_t)row * N + col]       = pack_half2(f0, f1);
                    *(uint32_t*)&C[(size_t)(row + 8) * N + col] = pack_half2(f2, f3);
                } else {
                    *(float2*)&C[(size_t)row * N + col]       = make_float2(f0, f1);
                    *(float2*)&C[(size_t)(row + 8) * N + col] = make_float2(f2, f3);
                }
            }
        }
    };

    if constexpr (AF32) cp_wait<1>();
    else                cp_wait<0>();
    __syncthreads();
    compute(Bs0, 0);
    __syncthreads();
    if (2 < NB) { issueB(2, Bs0); }

    for (int nt = 1; nt + 1 < NB; ++nt) {
        cp_wait<1>();
        __syncthreads();
        compute((nt & 1) ? Bs1 : Bs0, nt);
        __syncthreads();
        if (nt + 2 < NB) issueB(nt + 2, (nt & 1) ? Bs1 : Bs0);
    }
    cp_wait<0>();
    __syncthreads();
    compute(((NB - 1) & 1) ? Bs1 : Bs0, NB - 1);
}

// ---------------------------------------------------------------------------
// f16 neighborhood attention: max-free softmax, adjacent-row warp ownership,
// shared K/V fragments, packed f16x2 mask, and (NEW) software-pipelined
// K-fragment loads: iteration r+1's ldsm.x4 of K issues before iteration r's
// compute, hiding the ldsm->mma dependency that heads each iteration.
// ---------------------------------------------------------------------------
template <int KS>
__device__ __forceinline__ void na2d_body(
    const __half* __restrict__ qkv, __half* __restrict__ att,
    int b, int h, int g, __half* smh)
{
    constexpr int HS  = 16 + KS - 1;
    constexpr int NT  = (HS + 7) / 8;
    constexpr int PAD = 16;
    constexpr int PIX = HS * HS + PAD;
    constexpr int STR = 40;

    __half* Ks = smh;
    __half* Vs = smh + PIX * STR;

    const int tid = threadIdx.x;
    const int ti0 = blockIdx.y * 16;
    const int tj0 = blockIdx.x * 16;
    const int hi0 = min(max(ti0 - KS / 2, 0), 96 - KS);
    const int hj0 = min(max(tj0 - KS / 2, 0), 96 - KS);
    const int cb  = g * 192 + h * 32;
    const size_t bbase = (size_t)b * 96 * 96 * 576;

    {
        uint32_t* kp = (uint32_t*)(Ks + HS * HS * STR);
        uint32_t* vp = (uint32_t*)(Vs + HS * HS * STR);
        for (int i = tid; i < PAD * STR / 2; i += 256) { kp[i] = 0u; vp[i] = 0u; }
    }

    for (int idx = tid; idx < HS * HS * 4; idx += 256) {
        int p = idx >> 2, c = idx & 3;
        int hr = p / HS, hc = p % HS;
        int pi = min(hi0 + hr, 95);
        int pj = min(hj0 + hc, 95);
        const __half* src = &qkv[bbase + (size_t)(pi * 96 + pj) * 576 + cb];
        *(uint4*)&Ks[p * STR + c * 8] = *(const uint4*)(src + 64 + c * 8);
        *(uint4*)&Vs[p * STR + c * 8] = *(const uint4*)(src + 128 + c * 8);
    }
    __syncthreads();

    const int lane = tid & 31;
    const int warp = tid >> 5;
    const int lq = lane >> 2;
    const int lr = lane & 3;

    const int sj0 = min(max(tj0 + lq     - KS / 2, 0), 96 - KS) - hj0;
    const int sj1 = min(max(tj0 + lq + 8 - KS / 2, 0), 96 - KS) - hj0;
    uint32_t mbh[4][2];
#pragma unroll
    for (int nt = 0; nt < 4; ++nt) {
        int c0 = nt * 8 + 2 * lr, c1 = c0 + 1;
        uint32_t a0 = ((unsigned)(c0 - sj0) >= (unsigned)KS) ? 0xFC00u : 0u;
        uint32_t a1 = ((unsigned)(c1 - sj0) >= (unsigned)KS) ? 0xFC00u : 0u;
        uint32_t b0 = ((unsigned)(c0 - sj1) >= (unsigned)KS) ? 0xFC00u : 0u;
        uint32_t b1 = ((unsigned)(c1 - sj1) >= (unsigned)KS) ? 0xFC00u : 0u;
        mbh[nt][0] = a0 | (a1 << 16);
        mbh[nt][1] = b0 | (b1 << 16);
    }

    const int pi0 = ti0 + 2 * warp;
    const int pi1 = pi0 + 1;
    const int si0 = min(max(pi0 - KS / 2, 0), 96 - KS) - hi0;
    const int si1 = min(max(pi1 - KS / 2, 0), 96 - KS) - hi0;
    const int rlo = min(si0, si1);
    const int rhi = max(si0, si1) + KS;

    uint32_t aq0[2][4], aq1[2][4];
    {
        const __half* q0 = &qkv[bbase + ((size_t)pi0 * 96 + tj0 + lq) * 576 + cb + 2 * lr];
        const __half* q1 = q0 + 8 * 576;
        const __half* q2 = &qkv[bbase + ((size_t)pi1 * 96 + tj0 + lq) * 576 + cb + 2 * lr];
        const __half* q3 = q2 + 8 * 576;
#pragma unroll
        for (int kt = 0; kt < 2; ++kt) {
            aq0[kt][0] = *(const uint32_t*)(q0 + kt * 16);
            aq0[kt][1] = *(const uint32_t*)(q1 + kt * 16);
            aq0[kt][2] = *(const uint32_t*)(q0 + kt * 16 + 8);
            aq0[kt][3] = *(const uint32_t*)(q1 + kt * 16 + 8);
            aq1[kt][0] = *(const uint32_t*)(q2 + kt * 16);
            aq1[kt][1] = *(const uint32_t*)(q3 + kt * 16);
            aq1[kt][2] = *(const uint32_t*)(q2 + kt * 16 + 8);
            aq1[kt][3] = *(const uint32_t*)(q3 + kt * 16 + 8);
        }
    }

    float l00 = 0.f, l01 = 0.f, l10 = 0.f, l11 = 0.f;
    float o0[4][4], o1[4][4];
#pragma unroll
    for (int nt = 0; nt < 4; ++nt)
#pragma unroll
        for (int r = 0; r < 4; ++r) { o0[nt][r] = 0.f; o1[nt][r] = 0.f; }

    // K-fragment loader (NT ldsm.x4), V loader + full compute for one halo row
    auto loadK = [&](int r, uint32_t (&kb)[4][4]) {
        const int prow = r * HS;
#pragma unroll
        for (int nt = 0; nt < NT; ++nt)
            ldsm_x4(kb[nt], &Ks[(prow + nt * 8 + (lane & 7)) * STR + (lane >> 3) * 8]);
    };

    auto iterbody = [&](int r, const uint32_t (&kb)[4][4]) {
        const int prow = r * HS;
        uint32_t bv[2][2][4];
#pragma unroll
        for (int kt = 0; kt < 2; ++kt) {
            const __half* vp = &Vs[(prow + kt * 16 + (lane & 15)) * STR + (lane >> 4) * 8];
            ldsm_x4_trans(bv[kt][0], vp);
            ldsm_x4_trans(bv[kt][1], vp + 16);
        }

        const bool act0 = (r >= si0) && (r < si0 + KS);
        const bool act1 = (r >= si1) && (r < si1 + KS);

        auto step = [&](const uint32_t (&aq)[2][4], float (&o)[4][4],
                        float& lg0, float& lg1) {
            float scr[4][4];
            uint32_t ph[4][2];
#pragma unroll
            for (int nt = 0; nt < 4; ++nt) {
                if (nt < NT) {
                    scr[nt][0] = scr[nt][1] = scr[nt][2] = scr[nt][3] = 0.f;
                    mma_f16(scr[nt], aq[0][0], aq[0][1], aq[0][2], aq[0][3],
                            kb[nt][0], kb[nt][1]);
                    mma_f16(scr[nt], aq[1][0], aq[1][1], aq[1][2], aq[1][3],
                            kb[nt][2], kb[nt][3]);
                    ph[nt][0] = h2exp2(h2add(pack_half2(scr[nt][0], scr[nt][1]),
                                             mbh[nt][0]));
                    ph[nt][1] = h2exp2(h2add(pack_half2(scr[nt][2], scr[nt][3]),
                                             mbh[nt][1]));
                } else {
                    ph[nt][0] = 0u; ph[nt][1] = 0u;
                }
            }
            {
                uint32_t s0 = h2add(h2add(ph[0][0], ph[1][0]), h2add(ph[2][0], ph[3][0]));
                uint32_t s1 = h2add(h2add(ph[0][1], ph[1][1]), h2add(ph[2][1], ph[3][1]));
                float2 f0 = __half22float2(*(__half2*)&s0);
                float2 f1 = __half22float2(*(__half2*)&s1);
                lg0 += f0.x + f0.y;
                lg1 += f1.x + f1.y;
            }
#pragma unroll
            for (int kt = 0; kt < 2; ++kt) {
                uint32_t pa0 = ph[2 * kt][0],     pa1 = ph[2 * kt][1];
                uint32_t pa2 = ph[2 * kt + 1][0], pa3 = ph[2 * kt + 1][1];
#pragma unroll
                for (int np = 0; np < 2; ++np) {
                    mma_f16(o[2 * np],     pa0, pa1, pa2, pa3,
                            bv[kt][np][0], bv[kt][np][1]);
                    mma_f16(o[2 * np + 1], pa0, pa1, pa2, pa3,
                            bv[kt][np][2], bv[kt][np][3]);
                }
            }
        };

        if (act0) step(aq0, o0, l00, l01);
        if (act1) step(aq1, o1, l10, l11);
    };

    // Software-pipelined loop: K-frags for r+1 load before compute of r.
    // Unrolled x2 with fixed buffers (no dynamic register indexing).
    uint32_t kbA[4][4], kbB[4][4];
    loadK(rlo, kbA);
    for (int r = rlo; r < rhi; r += 2) {
        if (r + 1 < rhi) loadK(r + 1, kbB);
        iterbody(r, kbA);
        if (r + 1 < rhi) {
            if (r + 2 < rhi) loadK(r + 2, kbA);
            iterbody(r + 1, kbB);
        }
    }

    l00 += __shfl_xor_sync(0xffffffffu, l00, 1);
    l00 += __shfl_xor_sync(0xffffffffu, l00, 2);
    l01 += __shfl_xor_sync(0xffffffffu, l01, 1);
    l01 += __shfl_xor_sync(0xffffffffu, l01, 2);
    l10 += __shfl_xor_sync(0xffffffffu, l10, 1);
    l10 += __shfl_xor_sync(0xffffffffu, l10, 2);
    l11 += __shfl_xor_sync(0xffffffffu, l11, 1);
    l11 += __shfl_xor_sync(0xffffffffu, l11, 2);
    const float i00 = 1.f / l00, i01 = 1.f / l01;
    const float i10 = 1.f / l10, i11 = 1.f / l11;

    const size_t rb0 = ((size_t)(b * 96 * 96) + (size_t)pi0 * 96) * 192 + g * 64 + h * 32;
    const size_t rb1 = ((size_t)(b * 96 * 96) + (size_t)pi1 * 96) * 192 + g * 64 + h * 32;
    __half* o00p = &att[rb0 + (size_t)(tj0 + lq) * 192];
    __half* o01p = &att[rb0 + (size_t)(tj0 + lq + 8) * 192];
    __half* o10p = &att[rb1 + (size_t)(tj0 + lq) * 192];
    __half* o11p = &att[rb1 + (size_t)(tj0 + lq + 8) * 192];
#pragma unroll
    for (int nt = 0; nt < 4; ++nt) {
        *(uint32_t*)&o00p[nt * 8 + 2 * lr] = pack_half2(o0[nt][0] * i00, o0[nt][1] * i00);
        *(uint32_t*)&o01p[nt * 8 + 2 * lr] = pack_half2(o0[nt][2] * i01, o0[nt][3] * i01);
        *(uint32_t*)&o10p[nt * 8 + 2 * lr] = pack_half2(o1[nt][0] * i10, o1[nt][1] * i10);
        *(uint32_t*)&o11p[nt * 8 + 2 * lr] = pack_half2(o1[nt][2] * i11, o1[nt][3] * i11);
    }
}

__global__ void __launch_bounds__(256, 2) na2d_fused_kernel(
    const __half* __restrict__ qkv, __half* __restrict__ att)
{
    extern __shared__ __align__(16) __half smh[];
    const int z = blockIdx.z;
    const int g = z >> 3;
    const int b = (z & 7) >> 1;
    const int h = z & 1;
    if (g == 0)      na2d_body<7>(qkv, att, b, h, 0, smh);
    else if (g == 1) na2d_body<9>(qkv, att, b, h, 1, smh);
    else             na2d_body<11>(qkv, att, b, h, 2, smh);
}

// ---------------------------------------------------------------------------
// kernel_launch
// ---------------------------------------------------------------------------
extern "C" void kernel_launch(void* const* d_in, const int* in_sizes, int n_in,
                              void* d_out, int out_size)
{
    (void)in_sizes; (void)n_in; (void)out_size;
    const float* x      = (const float*)d_in[0];
    const float* w_qkv  = (const float*)d_in[1];
    const float* b_qkv  = (const float*)d_in[2];
    const float* w_proj = (const float*)d_in[3];
    const float* b_proj = (const float*)d_in[4];
    float* out = (float*)d_out;

    void *qkv_p, *att_p, *wqt_p, *wpt_p;
    cudaGetSymbolAddress(&qkv_p, g_qkv_h);
    cudaGetSymbolAddress(&att_p, g_att_h);
    cudaGetSymbolAddress(&wqt_p, g_wqkvt);
    cudaGetSymbolAddress(&wpt_p, g_wprojt);
    __half* qkv = (__half*)qkv_p;
    __half* att = (__half*)att_p;
    __half* wqt = (__half*)wqt_p;
    __half* wpt = (__half*)wpt_p;

    constexpr int smemG = (128 * 200 + 2 * 64 * 200) * 2;  // 102,400 B
    constexpr int smemA = 2 * (26 * 26 + 16) * 40 * 2;     // 110,720 B
    cudaFuncSetAttribute((const void*)gemm_persistA_kernel<true, __half, true, 9>,
                         cudaFuncAttributeMaxDynamicSharedMemorySize, smemG);
    cudaFuncSetAttribute((const void*)gemm_persistA_kernel<false, float, false, 3>,
                         cudaFuncAttributeMaxDynamicSharedMemorySize, smemG);
    cudaFuncSetAttribute(na2d_fused_kernel,
                         cudaFuncAttributeMaxDynamicSharedMemorySize, smemA);

    // 0) Weight transposes (one tiny launch)
    {
        int total = 192 * 576 + 192 * 192;
        transpose_weights_kernel<<<(total + 255) / 256, 256>>>(w_qkv, w_proj, wqt, wpt);
    }

    // 1) QKV GEMM: f32 x in (converted during A-stage) -> half out,
    //    q pre-scaled by 2^-2.5 * log2(e) (scores land in log2 domain)
    gemm_persistA_kernel<true, __half, true, 9><<<TOKENS / 128, 256, smemG>>>(
        x, wqt, b_qkv, qkv);

    // 2) Neighborhood attention, all three window sizes in one launch
    na2d_fused_kernel<<<dim3(6, 6, 24), 256, smemA>>>(qkv, att);

    // 3) Projection GEMM: half in -> f32 out
    gemm_persistA_kernel<false, float, false, 3><<<TOKENS / 128, 256, smemG>>>(
        att, wpt, b_proj, out);
}

// round 15
// speedup vs baseline: 1.5707x; 1.5707x over previous
#include <cuda_runtime.h>
#include <cuda_fp16.h>
#include <math.h>
#include <stdint.h>

// ---------------------------------------------------------------------------
// Problem constants
//   x:      (4, 96, 96, 192)  -> tokens = 36864
//   qkv:    tokens x 576 (half; q pre-scaled by 2^-2.5 * log2(e))
//   att:    tokens x 192 (half)
//   out:    tokens x 192 (float)
// ---------------------------------------------------------------------------
#define TOKENS (4 * 96 * 96)

__device__ unsigned short g_qkv_h[(size_t)TOKENS * 576]; // 42.5 MB half scratch
__device__ unsigned short g_att_h[(size_t)TOKENS * 192]; // 14.2 MB half scratch
__device__ unsigned short g_wqkvt[576 * 192];            // w_qkv^T half [N][K]
__device__ unsigned short g_wprojt[192 * 192];           // w_proj^T half [N][K]

__device__ __forceinline__ uint32_t pack_half2(float lo, float hi) {
    uint32_t r;
    asm("cvt.rn.f16x2.f32 %0, %1, %2;" : "=r"(r) : "f"(hi), "f"(lo));
    return r;
}
__device__ __forceinline__ uint32_t h2add(uint32_t a, uint32_t b) {
    uint32_t r;
    asm("add.f16x2 %0, %1, %2;" : "=r"(r) : "r"(a), "r"(b));
    return r;
}
__device__ __forceinline__ uint32_t h2exp2(uint32_t x) {
    uint32_t r;
    asm("ex2.approx.f16x2 %0, %1;" : "=r"(r) : "r"(x));
    return r;
}
__device__ __forceinline__ void mma_f16(float* d, uint32_t a0, uint32_t a1,
                                        uint32_t a2, uint32_t a3,
                                        uint32_t b0, uint32_t b1) {
    asm volatile(
        "mma.sync.aligned.m16n8k16.row.col.f32.f16.f16.f32 "
        "{%0,%1,%2,%3}, {%4,%5,%6,%7}, {%8,%9}, {%0,%1,%2,%3};\n"
        : "+f"(d[0]), "+f"(d[1]), "+f"(d[2]), "+f"(d[3])
        : "r"(a0), "r"(a1), "r"(a2), "r"(a3), "r"(b0), "r"(b1));
}
__device__ __forceinline__ void ldsm_x4(uint32_t* r, const __half* p) {
    uint32_t addr = (uint32_t)__cvta_generic_to_shared(p);
    asm volatile("ldmatrix.sync.aligned.m8n8.x4.shared.b16 {%0,%1,%2,%3}, [%4];"
                 : "=r"(r[0]), "=r"(r[1]), "=r"(r[2]), "=r"(r[3]) : "r"(addr));
}
__device__ __forceinline__ void ldsm_x4_trans(uint32_t* r, const __half* p) {
    uint32_t addr = (uint32_t)__cvta_generic_to_shared(p);
    asm volatile("ldmatrix.sync.aligned.m8n8.x4.trans.shared.b16 {%0,%1,%2,%3}, [%4];"
                 : "=r"(r[0]), "=r"(r[1]), "=r"(r[2]), "=r"(r[3]) : "r"(addr));
}
__device__ __forceinline__ void cp_async16(__half* dst, const __half* src) {
    uint32_t d = (uint32_t)__cvta_generic_to_shared(dst);
    asm volatile("cp.async.cg.shared.global [%0], [%1], 16;\n" :: "r"(d), "l"(src));
}
__device__ __forceinline__ void cp_commit() {
    asm volatile("cp.async.commit_group;\n");
}
template <int N>
__device__ __forceinline__ void cp_wait() {
    asm volatile("cp.async.wait_group %0;\n" :: "n"(N));
}

// ---------------------------------------------------------------------------
// Pre-pass: both weight transposes in ONE launch.
// ---------------------------------------------------------------------------
__global__ void __launch_bounds__(256) transpose_weights_kernel(
    const float* __restrict__ wq, const float* __restrict__ wp,
    __half* __restrict__ wqt, __half* __restrict__ wpt)
{
    int i = blockIdx.x * 256 + threadIdx.x;
    if (i < 192 * 576) {
        int k = i / 576, n = i % 576;
        wqt[n * 192 + k] = __float2half(wq[i]);
    } else {
        i -= 192 * 576;
        if (i < 192 * 192) {
            int k = i / 192, n = i % 192;
            wpt[n * 192 + k] = __float2half(wp[i]);
        }
    }
}

// ---------------------------------------------------------------------------
// Persistent-A f16 GEMM, K=192, 256 threads (8 warps: 4 M x 2 N) — R12 config.
// Warp tile 32x32 (2 mi x 4 ni). Double-buffered cp.async B over NB n-tiles.
// QSCALE: q blocks scaled by 2^-2.5 * log2(e)  (scores in log2 domain).
// ---------------------------------------------------------------------------
template <bool AF32, typename OT, bool QSCALE, int NB>
__global__ void __launch_bounds__(256) gemm_persistA_kernel(
    const void* __restrict__ Ap, const __half* __restrict__ BT,
    const float* __restrict__ bias, OT* __restrict__ C)
{
    constexpr int K = 192, STR = 200, N = NB * 64;
    extern __shared__ __align__(16) __half smg[];
    __half* As  = smg;
    __half* Bs0 = smg + 128 * STR;
    __half* Bs1 = Bs0 + 64 * STR;

    const int tid    = threadIdx.x;
    const int lane   = tid & 31;
    const int warpId = tid >> 5;
    const int wm     = warpId & 3;
    const int wn     = warpId >> 2;
    const int m0     = blockIdx.x * 128;
    const int lq = lane >> 2;
    const int lr = lane & 3;

    auto issueB = [&](int nt, __half* dst) {
#pragma unroll
        for (int i = 0; i < 6; ++i) {
            int idx = tid + i * 256;
            int row = idx / 24, c = idx % 24;
            cp_async16(&dst[row * STR + c * 8],
                       &BT[(size_t)(nt * 64 + row) * K + c * 8]);
        }
        cp_commit();
    };
    issueB(0, Bs0);
    issueB(1, Bs1);

    if constexpr (AF32) {
        const float* A = (const float*)Ap;
#pragma unroll
        for (int i = 0; i < 24; ++i) {
            int idx = tid + i * 256;
            int row = idx / 48, c = idx % 48;
            float4 v = *(const float4*)&A[(size_t)(m0 + row) * K + c * 4];
            uint2 u;
            u.x = pack_half2(v.x, v.y);
            u.y = pack_half2(v.z, v.w);
            *(uint2*)&As[row * STR + c * 4] = u;
        }
    } else {
        const __half* A = (const __half*)Ap;
#pragma unroll
        for (int i = 0; i < 12; ++i) {
            int idx = tid + i * 256;
            int row = idx / 24, c = idx % 24;
            cp_async16(&As[row * STR + c * 8], &A[(size_t)(m0 + row) * K + c * 8]);
        }
        cp_commit();
    }

    const __half* aA = &As[(wm * 32 + (lane & 15)) * STR + (lane >> 4) * 8];
    const int bOff = (wn * 32 + ((lane >> 4) & 1) * 8 + (lane & 7)) * STR
                     + ((lane >> 3) & 1) * 8;

    auto compute = [&](const __half* BsBuf, int nt) {
        float acc[2][4][4];
#pragma unroll
        for (int mi = 0; mi < 2; ++mi)
#pragma unroll
            for (int ni = 0; ni < 4; ++ni)
#pragma unroll
                for (int r = 0; r < 4; ++r) acc[mi][ni][r] = 0.f;

        const __half* aB = BsBuf + bOff;
#pragma unroll
        for (int kt = 0; kt < 12; ++kt) {
            uint32_t a[2][4], b[2][4];
            ldsm_x4(a[0], aA + kt * 16);
            ldsm_x4(a[1], aA + 16 * STR + kt * 16);
            ldsm_x4(b[0], aB + kt * 16);
            ldsm_x4(b[1], aB + 16 * STR + kt * 16);
#pragma unroll
            for (int mi = 0; mi < 2; ++mi)
#pragma unroll
                for (int p = 0; p < 2; ++p) {
                    mma_f16(acc[mi][2 * p],     a[mi][0], a[mi][1], a[mi][2], a[mi][3],
                            b[p][0], b[p][1]);
                    mma_f16(acc[mi][2 * p + 1], a[mi][0], a[mi][1], a[mi][2], a[mi][3],
                            b[p][2], b[p][3]);
                }
        }

        float s = 1.f;
        if (QSCALE && (nt % 3 == 0)) s = 0.25503519364597307f; // 2^-2.5 * log2(e)
        const int n0 = nt * 64;
#pragma unroll
        for (int mi = 0; mi < 2; ++mi) {
#pragma unroll
            for (int ni = 0; ni < 4; ++ni) {
                int row = m0 + wm * 32 + mi * 16 + lq;
                int col = n0 + wn * 32 + ni * 8 + 2 * lr;
                float2 bv = *(const float2*)&bias[col];
                float f0 = (acc[mi][ni][0] + bv.x) * s;
                float f1 = (acc[mi][ni][1] + bv.y) * s;
                float f2 = (acc[mi][ni][2] + bv.x) * s;
                float f3 = (acc[mi][ni][3] + bv.y) * s;
                if constexpr (sizeof(OT) == 2) {
                    *(uint32_t*)&C[(size_t)row * N + col]       = pack_half2(f0, f1);
                    *(uint32_t*)&C[(size_t)(row + 8) * N + col] = pack_half2(f2, f3);
                } else {
                    *(float2*)&C[(size_t)row * N + col]       = make_float2(f0, f1);
                    *(float2*)&C[(size_t)(row + 8) * N + col] = make_float2(f2, f3);
                }
            }
        }
    };

    if constexpr (AF32) cp_wait<1>();
    else                cp_wait<0>();
    __syncthreads();
    compute(Bs0, 0);
    __syncthreads();
    if (2 < NB) { issueB(2, Bs0); }

    for (int nt = 1; nt + 1 < NB; ++nt) {
        cp_wait<1>();
        __syncthreads();
        compute((nt & 1) ? Bs1 : Bs0, nt);
        __syncthreads();
        if (nt + 2 < NB) issueB(nt + 2, (nt & 1) ? Bs1 : Bs0);
    }
    cp_wait<0>();
    __syncthreads();
    compute(((NB - 1) & 1) ? Bs1 : Bs0, NB - 1);
}

// ---------------------------------------------------------------------------
// f16 neighborhood attention — R12 body (known-good) with ONE change:
// K/V staging via cp.async.cg, wait deferred past mask + Q-fragment setup.
// Max-free softmax, adjacent-row warp ownership, shared K/V fragments,
// packed f16x2 -inf mask before ex2.
// ---------------------------------------------------------------------------
template <int KS>
__device__ __forceinline__ void na2d_body(
    const __half* __restrict__ qkv, __half* __restrict__ att,
    int b, int h, int g, __half* smh)
{
    constexpr int HS  = 16 + KS - 1;
    constexpr int NT  = (HS + 7) / 8;
    constexpr int PAD = 16;
    constexpr int PIX = HS * HS + PAD;
    constexpr int STR = 40;

    __half* Ks = smh;
    __half* Vs = smh + PIX * STR;

    const int tid = threadIdx.x;
    const int ti0 = blockIdx.y * 16;
    const int tj0 = blockIdx.x * 16;
    const int hi0 = min(max(ti0 - KS / 2, 0), 96 - KS);
    const int hj0 = min(max(tj0 - KS / 2, 0), 96 - KS);
    const int cb  = g * 192 + h * 32;
    const size_t bbase = (size_t)b * 96 * 96 * 576;

    // Zero pad pixels (plain STS; disjoint from the cp.async region)
    {
        uint32_t* kp = (uint32_t*)(Ks + HS * HS * STR);
        uint32_t* vp = (uint32_t*)(Vs + HS * HS * STR);
        for (int i = tid; i < PAD * STR / 2; i += 256) { kp[i] = 0u; vp[i] = 0u; }
    }

    // Stage K, V via cp.async (overlapped with mask/Q setup below)
    for (int idx = tid; idx < HS * HS * 4; idx += 256) {
        int p = idx >> 2, c = idx & 3;
        int hr = p / HS, hc = p % HS;
        int pi = min(hi0 + hr, 95);
        int pj = min(hj0 + hc, 95);
        const __half* src = &qkv[bbase + (size_t)(pi * 96 + pj) * 576 + cb];
        cp_async16(&Ks[p * STR + c * 8], src + 64 + c * 8);
        cp_async16(&Vs[p * STR + c * 8], src + 128 + c * 8);
    }
    cp_commit();

    const int lane = tid & 31;
    const int warp = tid >> 5;
    const int lq = lane >> 2;
    const int lr = lane & 3;

    // Column mask as packed f16x2 (-inf for invalid cols); row-independent.
    const int sj0 = min(max(tj0 + lq     - KS / 2, 0), 96 - KS) - hj0;
    const int sj1 = min(max(tj0 + lq + 8 - KS / 2, 0), 96 - KS) - hj0;
    uint32_t mbh[4][2];
#pragma unroll
    for (int nt = 0; nt < 4; ++nt) {
        int c0 = nt * 8 + 2 * lr, c1 = c0 + 1;
        uint32_t a0 = ((unsigned)(c0 - sj0) >= (unsigned)KS) ? 0xFC00u : 0u;
        uint32_t a1 = ((unsigned)(c1 - sj0) >= (unsigned)KS) ? 0xFC00u : 0u;
        uint32_t b0 = ((unsigned)(c0 - sj1) >= (unsigned)KS) ? 0xFC00u : 0u;
        uint32_t b1 = ((unsigned)(c1 - sj1) >= (unsigned)KS) ? 0xFC00u : 0u;
        mbh[nt][0] = a0 | (a1 << 16);
        mbh[nt][1] = b0 | (b1 << 16);
    }

    // Warp owns adjacent query rows y0 = 2*warp, y1 = y0 + 1.
    const int pi0 = ti0 + 2 * warp;
    const int pi1 = pi0 + 1;
    const int si0 = min(max(pi0 - KS / 2, 0), 96 - KS) - hi0;
    const int si1 = min(max(pi1 - KS / 2, 0), 96 - KS) - hi0;
    const int rlo = min(si0, si1);
    const int rhi = max(si0, si1) + KS;

    // Q A-fragments straight from gmem (independent of smem staging).
    uint32_t aq0[2][4], aq1[2][4];
    {
        const __half* q0 = &qkv[bbase + ((size_t)pi0 * 96 + tj0 + lq) * 576 + cb + 2 * lr];
        const __half* q1 = q0 + 8 * 576;
        const __half* q2 = &qkv[bbase + ((size_t)pi1 * 96 + tj0 + lq) * 576 + cb + 2 * lr];
        const __half* q3 = q2 + 8 * 576;
#pragma unroll
        for (int kt = 0; kt < 2; ++kt) {
            aq0[kt][0] = *(const uint32_t*)(q0 + kt * 16);
            aq0[kt][1] = *(const uint32_t*)(q1 + kt * 16);
            aq0[kt][2] = *(const uint32_t*)(q0 + kt * 16 + 8);
            aq0[kt][3] = *(const uint32_t*)(q1 + kt * 16 + 8);
            aq1[kt][0] = *(const uint32_t*)(q2 + kt * 16);
            aq1[kt][1] = *(const uint32_t*)(q3 + kt * 16);
            aq1[kt][2] = *(const uint32_t*)(q2 + kt * 16 + 8);
            aq1[kt][3] = *(const uint32_t*)(q3 + kt * 16 + 8);
        }
    }

    // Now require the staged K/V.
    cp_wait<0>();
    __syncthreads();

    float l00 = 0.f, l01 = 0.f, l10 = 0.f, l11 = 0.f;
    float o0[4][4], o1[4][4];
#pragma unroll
    for (int nt = 0; nt < 4; ++nt)
#pragma unroll
        for (int r = 0; r < 4; ++r) { o0[nt][r] = 0.f; o1[nt][r] = 0.f; }

    for (int r = rlo; r < rhi; ++r) {
        const int prow = r * HS;

        // --- load K and V fragments ONCE for this halo row ---
        uint32_t kb[4][4];
#pragma unroll
        for (int nt = 0; nt < NT; ++nt)
            ldsm_x4(kb[nt], &Ks[(prow + nt * 8 + (lane & 7)) * STR + (lane >> 3) * 8]);
        uint32_t bv[2][2][4];
#pragma unroll
        for (int kt = 0; kt < 2; ++kt) {
            const __half* vp = &Vs[(prow + kt * 16 + (lane & 15)) * STR + (lane >> 4) * 8];
            ldsm_x4_trans(bv[kt][0], vp);
            ldsm_x4_trans(bv[kt][1], vp + 16);
        }

        const bool act0 = (r >= si0) && (r < si0 + KS);
        const bool act1 = (r >= si1) && (r < si1 + KS);

        auto step = [&](const uint32_t (&aq)[2][4], float (&o)[4][4],
                        float& lg0, float& lg1) {
            float scr[4][4];
            uint32_t ph[4][2];
#pragma unroll
            for (int nt = 0; nt < 4; ++nt) {
                if (nt < NT) {
                    scr[nt][0] = scr[nt][1] = scr[nt][2] = scr[nt][3] = 0.f;
                    mma_f16(scr[nt], aq[0][0], aq[0][1], aq[0][2], aq[0][3],
                            kb[nt][0], kb[nt][1]);
                    mma_f16(scr[nt], aq[1][0], aq[1][1], aq[1][2], aq[1][3],
                            kb[nt][2], kb[nt][3]);
                    ph[nt][0] = h2exp2(h2add(pack_half2(scr[nt][0], scr[nt][1]),
                                             mbh[nt][0]));
                    ph[nt][1] = h2exp2(h2add(pack_half2(scr[nt][2], scr[nt][3]),
                                             mbh[nt][1]));
                } else {
                    ph[nt][0] = 0u; ph[nt][1] = 0u;
                }
            }
            {
                uint32_t s0 = h2add(h2add(ph[0][0], ph[1][0]), h2add(ph[2][0], ph[3][0]));
                uint32_t s1 = h2add(h2add(ph[0][1], ph[1][1]), h2add(ph[2][1], ph[3][1]));
                float2 f0 = __half22float2(*(__half2*)&s0);
                float2 f1 = __half22float2(*(__half2*)&s1);
                lg0 += f0.x + f0.y;
                lg1 += f1.x + f1.y;
            }
#pragma unroll
            for (int kt = 0; kt < 2; ++kt) {
                uint32_t pa0 = ph[2 * kt][0],     pa1 = ph[2 * kt][1];
                uint32_t pa2 = ph[2 * kt + 1][0], pa3 = ph[2 * kt + 1][1];
#pragma unroll
                for (int np = 0; np < 2; ++np) {
                    mma_f16(o[2 * np],     pa0, pa1, pa2, pa3,
                            bv[kt][np][0], bv[kt][np][1]);
                    mma_f16(o[2 * np + 1], pa0, pa1, pa2, pa3,
                            bv[kt][np][2], bv[kt][np][3]);
                }
            }
        };

        if (act0) step(aq0, o0, l00, l01);
        if (act1) step(aq1, o1, l10, l11);
    }

    // --- epilogue: quad-reduce l once, normalize, store half ---
    l00 += __shfl_xor_sync(0xffffffffu, l00, 1);
    l00 += __shfl_xor_sync(0xffffffffu, l00, 2);
    l01 += __shfl_xor_sync(0xffffffffu, l01, 1);
    l01 += __shfl_xor_sync(0xffffffffu, l01, 2);
    l10 += __shfl_xor_sync(0xffffffffu, l10, 1);
    l10 += __shfl_xor_sync(0xffffffffu, l10, 2);
    l11 += __shfl_xor_sync(0xffffffffu, l11, 1);
    l11 += __shfl_xor_sync(0xffffffffu, l11, 2);
    const float i00 = 1.f / l00, i01 = 1.f / l01;
    const float i10 = 1.f / l10, i11 = 1.f / l11;

    const size_t rb0 = ((size_t)(b * 96 * 96) + (size_t)pi0 * 96) * 192 + g * 64 + h * 32;
    const size_t rb1 = ((size_t)(b * 96 * 96) + (size_t)pi1 * 96) * 192 + g * 64 + h * 32;
    __half* o00p = &att[rb0 + (size_t)(tj0 + lq) * 192];
    __half* o01p = &att[rb0 + (size_t)(tj0 + lq + 8) * 192];
    __half* o10p = &att[rb1 + (size_t)(tj0 + lq) * 192];
    __half* o11p = &att[rb1 + (size_t)(tj0 + lq + 8) * 192];
#pragma unroll
    for (int nt = 0; nt < 4; ++nt) {
        *(uint32_t*)&o00p[nt * 8 + 2 * lr] = pack_half2(o0[nt][0] * i00, o0[nt][1] * i00);
        *(uint32_t*)&o01p[nt * 8 + 2 * lr] = pack_half2(o0[nt][2] * i01, o0[nt][3] * i01);
        *(uint32_t*)&o10p[nt * 8 + 2 * lr] = pack_half2(o1[nt][0] * i10, o1[nt][1] * i10);
        *(uint32_t*)&o11p[nt * 8 + 2 * lr] = pack_half2(o1[nt][2] * i11, o1[nt][3] * i11);
    }
}

__global__ void __launch_bounds__(256, 2) na2d_fused_kernel(
    const __half* __restrict__ qkv, __half* __restrict__ att)
{
    extern __shared__ __align__(16) __half smh[];
    const int z = blockIdx.z;
    const int g = z >> 3;
    const int b = (z & 7) >> 1;
    const int h = z & 1;
    if (g == 0)      na2d_body<7>(qkv, att, b, h, 0, smh);
    else if (g == 1) na2d_body<9>(qkv, att, b, h, 1, smh);
    else             na2d_body<11>(qkv, att, b, h, 2, smh);
}

// ---------------------------------------------------------------------------
// kernel_launch
// ---------------------------------------------------------------------------
extern "C" void kernel_launch(void* const* d_in, const int* in_sizes, int n_in,
                              void* d_out, int out_size)
{
    (void)in_sizes; (void)n_in; (void)out_size;
    const float* x      = (const float*)d_in[0];
    const float* w_qkv  = (const float*)d_in[1];
    const float* b_qkv  = (const float*)d_in[2];
    const float* w_proj = (const float*)d_in[3];
    const float* b_proj = (const float*)d_in[4];
    float* out = (float*)d_out;

    void *qkv_p, *att_p, *wqt_p, *wpt_p;
    cudaGetSymbolAddress(&qkv_p, g_qkv_h);
    cudaGetSymbolAddress(&att_p, g_att_h);
    cudaGetSymbolAddress(&wqt_p, g_wqkvt);
    cudaGetSymbolAddress(&wpt_p, g_wprojt);
    __half* qkv = (__half*)qkv_p;
    __half* att = (__half*)att_p;
    __half* wqt = (__half*)wqt_p;
    __half* wpt = (__half*)wpt_p;

    constexpr int smemG = (128 * 200 + 2 * 64 * 200) * 2;  // 102,400 B
    constexpr int smemA = 2 * (26 * 26 + 16) * 40 * 2;     // 110,720 B
    cudaFuncSetAttribute((const void*)gemm_persistA_kernel<true, __half, true, 9>,
                         cudaFuncAttributeMaxDynamicSharedMemorySize, smemG);
    cudaFuncSetAttribute((const void*)gemm_persistA_kernel<false, float, false, 3>,
                         cudaFuncAttributeMaxDynamicSharedMemorySize, smemG);
    cudaFuncSetAttribute(na2d_fused_kernel,
                         cudaFuncAttributeMaxDynamicSharedMemorySize, smemA);

    // 0) Weight transposes (one tiny launch)
    {
        int total = 192 * 576 + 192 * 192;
        transpose_weights_kernel<<<(total + 255) / 256, 256>>>(w_qkv, w_proj, wqt, wpt);
    }

    // 1) QKV GEMM: f32 x in (converted during A-stage) -> half out,
    //    q pre-scaled by 2^-2.5 * log2(e) (scores land in log2 domain)
    gemm_persistA_kernel<true, __half, true, 9><<<TOKENS / 128, 256, smemG>>>(
        x, wqt, b_qkv, qkv);

    // 2) Neighborhood attention, all three window sizes in one launch
    na2d_fused_kernel<<<dim3(6, 6, 24), 256, smemA>>>(qkv, att);

    // 3) Projection GEMM: half in -> f32 out
    gemm_persistA_kernel<false, float, false, 3><<<TOKENS / 128, 256, smemG>>>(
        att, wpt, b_proj, out);
}